// round 9
// baseline (speedup 1.0000x reference)
#include <cuda_runtime.h>

// Fixed shapes
#define KDIM   51
#define KP2    56                // K padded to 56 (7 tiles of 8); 51=real, 51=ones(EPS), 52-55=zero
#define BDIM   256
#define CCOLS  24576             // 8192 points * 3
#define TCOLS  192               // columns per gram block (64 per d)
#define GBLKS  128               // gram blocks (1/SM, all co-resident)
#define QBLKS  32                // blocks that continue into the quad phase
#define NTHR   288               // 9 warps
#define COLS_D 64                // columns per d per block
#define CPAD   56                // k-extent per smem column (== KP2)
#define NT8    7                 // 56/8 k-tiles
#define NPAIR8 28                // upper-tri 8x8 tile pairs
#define NCOMBO 84                // 28 * 3 d
#define NITEM  168               // combos x 2 column-halves
#define NV4    (KDIM * TCOLS / 4)  // 2448 float4 loads per block
#define NLOAD  9                   // ceil(2448 / 288)
#define GFLTS  (3 * KP2 * KP2)     // 9408
#define EPSF   1e-6f
#define MULTF  0.0025f

// Self-resetting device state (zero-init at module load; finisher resets).
__device__ __align__(16) float g_G[GFLTS];
__device__ float    g_out;
__device__ unsigned g_ctr1;
__device__ unsigned g_ctr2;

typedef unsigned long long ull;

__device__ __forceinline__ ull pack2(float a, float b) {
    ull r; asm("mov.b64 %0, {%1, %2};" : "=l"(r) : "f"(a), "f"(b)); return r;
}
__device__ __forceinline__ void unpack2(ull v, float& a, float& b) {
    asm("mov.b64 {%0, %1}, %2;" : "=f"(a), "=f"(b) : "l"(v));
}
__device__ __forceinline__ void ffma2(ull& d, ull a, ull b) {
    asm("fma.rn.f32x2 %0, %1, %2, %0;" : "+l"(d) : "l"(a), "l"(b));
}

__global__ void __launch_bounds__(NTHR, 1)
fused_kernel(const float* __restrict__ bs,
             const float* __restrict__ y_hat,
             const float* __restrict__ y,
             float* __restrict__ out) {
    // Phase 1: As[3][COLS_D][CPAD] = 10752 floats (43008 B)
    // Phase 2 (same buffer): G_s (9408) + w_s (448) = 9856 floats
    __shared__ __align__(16) float smem[3 * COLS_D * CPAD];
    __shared__ bool s_last;

    const int tid = threadIdx.x;
    const int blk = blockIdx.x;

    // ---- Prefetch w operands for quad blocks (latency hidden by phase 1) ----
    float wpre[2];
    int   widx[2];
    const bool is_quad = (blk < QBLKS);
#pragma unroll
    for (int j = 0; j < 2; j++) {
        int i = tid + j * NTHR;            // 0..575, need < 448
        widx[j] = i;
        wpre[j] = 0.0f;
        if (is_quad && i < 8 * KP2) {
            int bl = i / KP2, k = i - bl * KP2;
            if (k < KDIM) {
                int gi = (blk * 8 + bl) * KDIM + k;
                wpre[j] = __ldg(&y_hat[gi]) - __ldg(&y[gi]);
            } else if (k == KDIM) {
                wpre[j] = EPSF;            // ones-row weight carries EPS
            }
        }
    }

    // ======================= Phase 1: Gram =======================
    {
        const int c0 = blk * TCOLS;
        // Front-batched loads: 9 independent LDG.128 per thread (MLP ~9).
        float4 vals[NLOAD];
        int    vv[NLOAD];
#pragma unroll
        for (int i = 0; i < NLOAD; i++) {
            int v = tid + i * NTHR;
            vv[i] = v;
            if (v < NV4) {
                int k = v / 48;            // 48 float4 per row
                int q = v - k * 48;
                vals[i] = *reinterpret_cast<const float4*>(
                    bs + (size_t)k * CCOLS + c0 + q * 4);
            }
        }
        // De-interleave stores: c = q*4 + j; d = c%3, col = c/3.
#pragma unroll
        for (int i = 0; i < NLOAD; i++) {
            if (vv[i] < NV4) {
                int k  = vv[i] / 48;
                int q  = vv[i] - k * 48;
                int c  = q * 4;
                int q3 = c % 3;
                int qc = c / 3;
                float x[4] = {vals[i].x, vals[i].y, vals[i].z, vals[i].w};
#pragma unroll
                for (int j = 0; j < 4; j++) {
                    int t   = q3 + j;              // 0..5
                    int add = (t >= 3) ? 1 : 0;
                    int d   = t - 3 * add;
                    int col = qc + add;
                    smem[(d * COLS_D + col) * CPAD + k] = x[j];
                }
            }
        }
        // Ones row (k=51) + zero pad rows (k=52..55) per (d,col).
        if (tid < TCOLS) {
            int d = tid % 3, col = tid / 3;
            float* p = smem + (d * COLS_D + col) * CPAD;
            p[KDIM] = 1.0f;
            *reinterpret_cast<float4*>(p + 52) =
                make_float4(0.0f, 0.0f, 0.0f, 0.0f);
        }
        __syncthreads();

        // 168 work items: (84 combos) x (2 column halves). <=1 per thread.
        if (tid < NITEM) {
            int item  = tid;
            int half  = item & 1;
            int combo = (item >> 1) + blk * 29;    // 29 coprime to 84
            combo %= NCOMBO;

            int d2   = combo / NPAIR8;
            int pair = combo - d2 * NPAIR8;
            int ti = 0, rem = pair;
            while (rem >= NT8 - ti) { rem -= NT8 - ti; ti++; }
            int tj = ti + rem;  // ti <= tj

            // 8x8 tile: acc2[rp][c] = (G[2rp][c], G[2rp+1][c]) packed pairs.
            ull acc2[4][8];
#pragma unroll
            for (int rp = 0; rp < 4; rp++)
#pragma unroll
                for (int c = 0; c < 8; c++) acc2[rp][c] = 0ull;

            const float* base = smem + d2 * COLS_D * CPAD + half * 32 * CPAD;
#pragma unroll 4
            for (int col = 0; col < 32; col++) {
                const float* cp = base + col * CPAD;
                // a: rows ti*8..ti*8+7 as 4 packed pairs (2x LDS.128)
                longlong2 qa0 = *reinterpret_cast<const longlong2*>(cp + ti * 8);
                longlong2 qa1 = *reinterpret_cast<const longlong2*>(cp + ti * 8 + 4);
                ull ap[4] = {(ull)qa0.x, (ull)qa0.y, (ull)qa1.x, (ull)qa1.y};
                // b: rows tj*8..tj*8+7, duplicated into 8 packed (2x LDS.128)
                float4 b0 = *reinterpret_cast<const float4*>(cp + tj * 8);
                float4 b1 = *reinterpret_cast<const float4*>(cp + tj * 8 + 4);
                ull bb[8] = {pack2(b0.x, b0.x), pack2(b0.y, b0.y),
                             pack2(b0.z, b0.z), pack2(b0.w, b0.w),
                             pack2(b1.x, b1.x), pack2(b1.y, b1.y),
                             pack2(b1.z, b1.z), pack2(b1.w, b1.w)};
#pragma unroll
                for (int rp = 0; rp < 4; rp++)
#pragma unroll
                    for (int c = 0; c < 8; c++)
                        ffma2(acc2[rp][c], ap[rp], bb[c]);
            }

            // Emit: rows 8ti+2rp(+1), cols 8tj..8tj+7 (two float4 per row).
#pragma unroll
            for (int rp = 0; rp < 4; rp++) {
                float r0[8], r1[8];
#pragma unroll
                for (int c = 0; c < 8; c++) unpack2(acc2[rp][c], r0[c], r1[c]);
                int row0 = ti * 8 + 2 * rp;
                float* gbase0 = &g_G[d2 * KP2 * KP2 + row0 * KP2 + tj * 8];
                float* gbase1 = gbase0 + KP2;
                atomicAdd(reinterpret_cast<float4*>(gbase0),
                          make_float4(r0[0], r0[1], r0[2], r0[3]));
                atomicAdd(reinterpret_cast<float4*>(gbase0 + 4),
                          make_float4(r0[4], r0[5], r0[6], r0[7]));
                atomicAdd(reinterpret_cast<float4*>(gbase1),
                          make_float4(r1[0], r1[1], r1[2], r1[3]));
                atomicAdd(reinterpret_cast<float4*>(gbase1 + 4),
                          make_float4(r1[4], r1[5], r1[6], r1[7]));
            }
        }
    }
    __syncthreads();   // all LDS of As done -> safe to repurpose smem
    if (tid == 0) {
        __threadfence();
        atomicAdd(&g_ctr1, 1u);
    }

    if (!is_quad) return;

    // Stash prefetched w while the barrier is pending.
    float* G_s = smem;                  // 9408 floats
    float* w_s = smem + GFLTS;          // 448 floats
#pragma unroll
    for (int j = 0; j < 2; j++)
        if (widx[j] < 8 * KP2) w_s[widx[j]] = wpre[j];

    // Grid-wide barrier: all 128 gram blocks are co-resident (1/SM).
    if (tid == 0) {
        while (atomicAdd(&g_ctr1, 0u) < (unsigned)GBLKS) { }
    }
    __syncthreads();

    // ======================= Phase 2: Quad =======================
    // Batched vector reload of G (9x float4 per thread, MLP 9).
    {
        float4 gv[9];
        int    gi[9];
#pragma unroll
        for (int i = 0; i < 9; i++) {
            int v = tid + i * NTHR;        // need < 2352
            gi[i] = v;
            if (v < GFLTS / 4)
                gv[i] = __ldcg(reinterpret_cast<const float4*>(g_G) + v);
        }
#pragma unroll
        for (int i = 0; i < 9; i++)
            if (gi[i] < GFLTS / 4)
                reinterpret_cast<float4*>(G_s)[gi[i]] = gv[i];
    }
    __syncthreads();

    const int wid  = tid >> 5;
    const int lane = tid & 31;

    if (wid < 8) {
        const int k1   = lane;             // 0..31
        const int k2v  = lane + 32;        // 32..63
        const bool has2 = (k2v < KP2);     // lanes 0..23
        const int k2   = has2 ? k2v : 0;

        const float* w = w_s + wid * KP2;
        const float wk1 = w[k1];
        const float wk2 = has2 ? w[k2v] : 0.0f;

        float total = 0.0f;
        for (int d = 0; d < 3; d++) {
            const float* G = G_s + d * KP2 * KP2;
            float t1 = 0.0f, t2 = 0.0f;
#pragma unroll 4
            for (int k = 0; k < KP2; k++) {
                float wk = w[k];
                float g1 = G[k * KP2 + k1];
                float g2 = G[k * KP2 + k2];
                float f1 = (k < k1)  ? wk : ((k == k1)  ? 0.5f * wk : 0.0f);
                float f2 = (k < k2v) ? wk : ((k == k2v) ? 0.5f * wk : 0.0f);
                t1 += g1 * f1;
                t2 += g2 * f2;
            }
            float p = 2.0f * (wk1 * t1 + wk2 * t2);
#pragma unroll
            for (int o = 16; o > 0; o >>= 1)
                p += __shfl_down_sync(0xFFFFFFFFu, p, o);
            if (lane == 0) total += sqrtf(p);
        }
        if (lane == 0) atomicAdd(&g_out, total);
    }

    // ======================= Finisher =======================
    __syncthreads();
    if (tid == 0) {
        __threadfence();
        unsigned old = atomicAdd(&g_ctr2, 1u);
        s_last = (old == (unsigned)(QBLKS - 1));
    }
    __syncthreads();
    if (!s_last) return;

    if (tid == 0) {
        float v = atomicAdd(&g_out, 0.0f);
        out[0] = v * MULTF;
    }
    for (int i = tid; i < GFLTS; i += NTHR) g_G[i] = 0.0f;
    if (tid == 0) {
        g_out  = 0.0f;
        g_ctr1 = 0u;
        g_ctr2 = 0u;
    }
}

extern "C" void kernel_launch(void* const* d_in, const int* in_sizes, int n_in,
                              void* d_out, int out_size) {
    const float* y_hat = (const float*)d_in[0];  // [256, 51]
    const float* y     = (const float*)d_in[1];  // [256, 51]
    // d_in[2] = face — cancels out of the loss, unused
    const float* bs    = (const float*)d_in[3];  // [51, 8192, 3]
    float* out = (float*)d_out;

    fused_kernel<<<GBLKS, NTHR>>>(bs, y_hat, y, out);
}

// round 10
// speedup vs baseline: 1.2145x; 1.2145x over previous
#include <cuda_runtime.h>

// Fixed shapes
#define KDIM   51
#define KP     52                // padded K (row 51 = ones, carries EPS exactly)
#define BDIM   256
#define CCOLS  24576             // 8192 points * 3
#define TCOLS  192               // columns per gram block (64 per d)
#define GBLKS  128               // gram blocks (1/SM, all co-resident)
#define QBLKS  32                // blocks that continue into the quad phase
#define NTHR   288               // 9 warps; 273 combos -> <=1 per thread
#define COLS_D 64                // columns per d per block
#define CPAD   56                // padded k-extent (multiple of 4 for LDS.128)
#define NTILE  13                // 52/4 k-tiles
#define NPAIRT 91                // upper-tri tile pairs
#define NCOMBO 273               // 91 * 3 d
#define NV4    (KDIM * TCOLS / 4)  // 2448 float4 loads per block
#define NLOAD  9                   // ceil(2448 / 288)
#define GFLTS  (3 * KP * KP)       // 8112
#define NPOS4  (GFLTS / 4)         // 2028 float4 positions
#define EPSF   1e-6f
#define MULTF  0.0025f

// Device state. Counters/g_out are zero-init and reset by the finisher;
// g_G and g_slab are fully overwritten every run.
__device__ __align__(16) float  g_G[GFLTS];
__device__ __align__(16) float4 g_slab[GBLKS * NPOS4];   // 4.15 MB
__device__ float    g_out;
__device__ unsigned g_ctr1;   // gram+slab done
__device__ unsigned g_ctr2;   // reduce done
__device__ unsigned g_ctr3;   // quad done

typedef unsigned long long ull;

__device__ __forceinline__ ull pack2(float a, float b) {
    ull r; asm("mov.b64 %0, {%1, %2};" : "=l"(r) : "f"(a), "f"(b)); return r;
}
__device__ __forceinline__ void unpack2(ull v, float& a, float& b) {
    asm("mov.b64 {%0, %1}, %2;" : "=f"(a), "=f"(b) : "l"(v));
}
__device__ __forceinline__ void ffma2(ull& d, ull a, ull b) {
    asm("fma.rn.f32x2 %0, %1, %2, %0;" : "+l"(d) : "l"(a), "l"(b));
}

__global__ void __launch_bounds__(NTHR, 1)
fused_kernel(const float* __restrict__ bs,
             const float* __restrict__ y_hat,
             const float* __restrict__ y,
             float* __restrict__ out) {
    // Phase 1: As[3][COLS_D][CPAD] = 10752 floats (43008 B)
    // Phase 3 (same buffer): G_s (8112 floats) + w_s (416 floats)
    __shared__ __align__(16) float smem[3 * COLS_D * CPAD];
    __shared__ bool s_last;

    const int tid = threadIdx.x;
    const int blk = blockIdx.x;

    // ---- Prefetch w operands for quad blocks (latency hidden by phase 1) ----
    float wpre[2];
    int   widx[2];
    const bool is_quad = (blk < QBLKS);
#pragma unroll
    for (int j = 0; j < 2; j++) {
        int i = tid + j * NTHR;            // 0..575, need < 416
        widx[j] = i;
        wpre[j] = EPSF;
        if (is_quad && i < 8 * KP) {
            int bl = i / KP, k = i - bl * KP;
            if (k < KDIM) {
                int gi = (blk * 8 + bl) * KDIM + k;
                wpre[j] = __ldg(&y_hat[gi]) - __ldg(&y[gi]);
            }
        }
    }

    // ======================= Phase 1: Gram =======================
    {
        const int c0 = blk * TCOLS;
        // Front-batched loads: 9 independent LDG.128 per thread (MLP ~9).
        float4 vals[NLOAD];
        int    vv[NLOAD];
#pragma unroll
        for (int i = 0; i < NLOAD; i++) {
            int v = tid + i * NTHR;
            vv[i] = v;
            if (v < NV4) {
                int k = v / 48;            // 48 float4 per row
                int q = v - k * 48;
                vals[i] = *reinterpret_cast<const float4*>(
                    bs + (size_t)k * CCOLS + c0 + q * 4);
            }
        }
        // Zero this block's slab under the LDG shadow (lower-tri stays 0).
        {
            float4 z = make_float4(0.0f, 0.0f, 0.0f, 0.0f);
            for (int i = tid; i < NPOS4; i += NTHR)
                g_slab[blk * NPOS4 + i] = z;
        }
        // De-interleave stores: c = q*4 + j; d = c%3, col = c/3.
#pragma unroll
        for (int i = 0; i < NLOAD; i++) {
            if (vv[i] < NV4) {
                int k  = vv[i] / 48;
                int q  = vv[i] - k * 48;
                int c  = q * 4;
                int q3 = c % 3;
                int qc = c / 3;
                float x[4] = {vals[i].x, vals[i].y, vals[i].z, vals[i].w};
#pragma unroll
                for (int j = 0; j < 4; j++) {
                    int t   = q3 + j;              // 0..5
                    int add = (t >= 3) ? 1 : 0;
                    int d   = t - 3 * add;
                    int col = qc + add;
                    smem[(d * COLS_D + col) * CPAD + k] = x[j];
                }
            }
        }
        // Ones row (k = 51): carries EPS cross & square terms exactly.
        if (tid < TCOLS) {
            int d = tid % 3, col = tid / 3;
            smem[(d * COLS_D + col) * CPAD + KDIM] = 1.0f;
        }
        __syncthreads();

        // <=1 combo per thread, staggered across blocks (37 coprime to 273).
        if (tid < NCOMBO) {
            int combo = (tid + blk * 37) % NCOMBO;
            int d2   = combo / NPAIRT;
            int tile = combo - d2 * NPAIRT;
            int ti = 0, rem = tile;
            while (rem >= NTILE - ti) { rem -= NTILE - ti; ti++; }
            int tj = ti + rem;  // ti <= tj

            ull acc2[2][4];
#pragma unroll
            for (int p = 0; p < 2; p++)
#pragma unroll
                for (int s = 0; s < 4; s++) acc2[p][s] = 0ull;

            const float* base = smem + d2 * COLS_D * CPAD;
#pragma unroll 8
            for (int col2 = 0; col2 < COLS_D; col2++) {
                longlong2 a = *reinterpret_cast<const longlong2*>(
                    base + col2 * CPAD + ti * 4);
                float4 b = *reinterpret_cast<const float4*>(
                    base + col2 * CPAD + tj * 4);
                ull bx = pack2(b.x, b.x), by = pack2(b.y, b.y);
                ull bz = pack2(b.z, b.z), bw = pack2(b.w, b.w);
                ffma2(acc2[0][0], (ull)a.x, bx);
                ffma2(acc2[0][1], (ull)a.x, by);
                ffma2(acc2[0][2], (ull)a.x, bz);
                ffma2(acc2[0][3], (ull)a.x, bw);
                ffma2(acc2[1][0], (ull)a.y, bx);
                ffma2(acc2[1][1], (ull)a.y, by);
                ffma2(acc2[1][2], (ull)a.y, bz);
                ffma2(acc2[1][3], (ull)a.y, bw);
            }

            // Plain stores into this block's private slab (no atomics).
            float* myslab = reinterpret_cast<float*>(g_slab + blk * NPOS4);
#pragma unroll
            for (int p = 0; p < 2; p++) {
                float r0x, r1x, r0y, r1y, r0z, r1z, r0w, r1w;
                unpack2(acc2[p][0], r0x, r1x);
                unpack2(acc2[p][1], r0y, r1y);
                unpack2(acc2[p][2], r0z, r1z);
                unpack2(acc2[p][3], r0w, r1w);
                int r0 = ti * 4 + 2 * p;
                *reinterpret_cast<float4*>(
                    myslab + d2 * KP * KP + r0 * KP + tj * 4) =
                    make_float4(r0x, r0y, r0z, r0w);
                *reinterpret_cast<float4*>(
                    myslab + d2 * KP * KP + (r0 + 1) * KP + tj * 4) =
                    make_float4(r1x, r1y, r1z, r1w);
            }
        }
    }
    __syncthreads();   // all LDS of As done -> safe to repurpose smem

    // Stash prefetched w into the (now dead) As region for quad blocks.
    float* G_s = smem;                 // 8112 floats
    float* w_s = smem + GFLTS;         // 416 floats
    if (is_quad) {
#pragma unroll
        for (int j = 0; j < 2; j++)
            if (widx[j] < 8 * KP) w_s[widx[j]] = wpre[j];
    }

    if (tid == 0) {
        __threadfence();
        atomicAdd(&g_ctr1, 1u);
        // Barrier 1: all slabs written (all 128 blocks co-resident, 1/SM).
        while (atomicAdd(&g_ctr1, 0u) < (unsigned)GBLKS) { }
    }
    __syncthreads();

    // ============ Phase 2: distributed slab reduce (all blocks) ============
    if (tid < 256) {
        int pos  = blk * 16 + (tid >> 4);
        int grp  = tid & 15;
        bool valid = (pos < NPOS4);
        float4 acc = make_float4(0.0f, 0.0f, 0.0f, 0.0f);
        if (valid) {
            const float4* sp = g_slab + pos + grp * 8 * NPOS4;
#pragma unroll
            for (int s = 0; s < 8; s++) {
                float4 v = __ldcg(sp + s * NPOS4);
                acc.x += v.x; acc.y += v.y; acc.z += v.z; acc.w += v.w;
            }
        }
        // Reduce across the 16 grp-lanes (width-16 shuffles, warp converged).
#pragma unroll
        for (int o = 8; o > 0; o >>= 1) {
            acc.x += __shfl_down_sync(0xFFFFFFFFu, acc.x, o, 16);
            acc.y += __shfl_down_sync(0xFFFFFFFFu, acc.y, o, 16);
            acc.z += __shfl_down_sync(0xFFFFFFFFu, acc.z, o, 16);
            acc.w += __shfl_down_sync(0xFFFFFFFFu, acc.w, o, 16);
        }
        if (valid && grp == 0)
            reinterpret_cast<float4*>(g_G)[pos] = acc;
    }
    __syncthreads();
    if (tid == 0) {
        __threadfence();
        atomicAdd(&g_ctr2, 1u);
    }

    if (!is_quad) return;

    // Barrier 2: final G ready.
    if (tid == 0) {
        while (atomicAdd(&g_ctr2, 0u) < (unsigned)GBLKS) { }
    }
    __syncthreads();

    // ======================= Phase 3: Quad =======================
    // Batched vector reload of G (8x float4 per thread, MLP 8).
    {
        float4 gv[8];
        int    gi[8];
#pragma unroll
        for (int i = 0; i < 8; i++) {
            int v = tid + i * NTHR;
            gi[i] = v;
            if (v < NPOS4)
                gv[i] = __ldcg(reinterpret_cast<const float4*>(g_G) + v);
        }
#pragma unroll
        for (int i = 0; i < 8; i++)
            if (gi[i] < NPOS4)
                reinterpret_cast<float4*>(G_s)[gi[i]] = gv[i];
    }
    __syncthreads();

    const int wid  = tid >> 5;
    const int lane = tid & 31;

    if (wid < 8) {
        const int k1   = lane;
        const int k2v  = lane + 32;
        const bool has2 = (k2v < KP);
        const int k2   = has2 ? k2v : KDIM;

        const float* w = w_s + wid * KP;
        const float wk1 = w[k1];
        const float wk2 = has2 ? w[k2v] : 0.0f;

        float total = 0.0f;
        for (int d = 0; d < 3; d++) {
            const float* G = G_s + d * KP * KP;
            float t1 = 0.0f, t2 = 0.0f;
#pragma unroll 4
            for (int k = 0; k < KP; k++) {
                float wk = w[k];
                float g1 = G[k * KP + k1];
                float g2 = G[k * KP + k2];
                float f1 = (k < k1)  ? wk : ((k == k1)  ? 0.5f * wk : 0.0f);
                float f2 = (k < k2v) ? wk : ((k == k2v) ? 0.5f * wk : 0.0f);
                t1 += g1 * f1;
                t2 += g2 * f2;
            }
            float p = 2.0f * (wk1 * t1 + wk2 * t2);
#pragma unroll
            for (int o = 16; o > 0; o >>= 1)
                p += __shfl_down_sync(0xFFFFFFFFu, p, o);
            if (lane == 0) total += sqrtf(p);
        }
        if (lane == 0) atomicAdd(&g_out, total);
    }

    // ======================= Finisher =======================
    __syncthreads();
    if (tid == 0) {
        __threadfence();
        unsigned old = atomicAdd(&g_ctr3, 1u);
        s_last = (old == (unsigned)(QBLKS - 1));
    }
    __syncthreads();
    if (!s_last) return;

    if (tid == 0) {
        float v = atomicAdd(&g_out, 0.0f);
        out[0] = v * MULTF;
        g_out  = 0.0f;
        g_ctr1 = 0u;
        g_ctr2 = 0u;
        g_ctr3 = 0u;
    }
}

extern "C" void kernel_launch(void* const* d_in, const int* in_sizes, int n_in,
                              void* d_out, int out_size) {
    const float* y_hat = (const float*)d_in[0];  // [256, 51]
    const float* y     = (const float*)d_in[1];  // [256, 51]
    // d_in[2] = face — cancels out of the loss, unused
    const float* bs    = (const float*)d_in[3];  // [51, 8192, 3]
    float* out = (float*)d_out;

    fused_kernel<<<GBLKS, NTHR>>>(bs, y_hat, y, out);
}